// round 12
// baseline (speedup 1.0000x reference)
#include <cuda_runtime.h>
#include <cuda_fp16.h>

#define N_NODES 60000
#define N_EDGES 1200000
#define D 64
#define CAP 128                      // bucket capacity per node (max deg ~50)

// ---------------- scratch (no allocations allowed; zero-init at load) -------
__device__ int     g_fill[N_NODES];          // cursor; re-zeroed each replay
__device__ int     g_degv[N_NODES];          // PADDED degree (multiple of 8)
__device__ int     g_edges[N_NODES * CAP];   // bucketed PRESCALED offs (src*32)
__device__ float   g_dinv[N_NODES];          // 1/sqrt(max(deg,1))
__device__ float   g_dsq [N_NODES];          // sqrt(max(deg,1))
// row N_NODES is a permanent zero row (never written) used by sentinel pads
__device__ __half2 g_xs0[(N_NODES + 1) * 32];  // X0 * dinv (fp16)
__device__ __half2 g_xs1[(N_NODES + 1) * 32];  // X1 * dinv (fp16)

// ---------------- build: coarsened atomic fill (2 edges/thread) +
//                  float4 relu(X0) stream ------------------------------------
__global__ void k_fill_relu(const int* __restrict__ src, const int* __restrict__ dst,
                            const float* __restrict__ feat, float* __restrict__ out,
                            int e, int n) {
    int i = blockIdx.x * blockDim.x + threadIdx.x;
    int eh = (e + 1) >> 1;
    if (i < eh) {                         // two independent edges per thread
        int d0 = dst[i];
        int s0 = src[i] * 32;
        int j2 = i + eh;
        int p0 = atomicAdd(&g_fill[d0], 1);
        if (j2 < e) {
            int d1 = dst[j2];
            int s1 = src[j2] * 32;
            int p1 = atomicAdd(&g_fill[d1], 1);
            if (p1 < CAP) g_edges[d1 * CAP + p1] = s1;
        }
        if (p0 < CAP) g_edges[d0 * CAP + p0] = s0;
    }
    if (i < n * 16) {                     // float4 per thread: out[:,0:64]=relu(feat)
        int row = i >> 4;
        int q   = i & 15;
        float4 f = ((const float4*)feat)[i];
        ((float4*)(out + (size_t)row * 192))[q] =
            make_float4(fmaxf(f.x, 0.f), fmaxf(f.y, 0.f),
                        fmaxf(f.z, 0.f), fmaxf(f.w, 0.f));
    }
}

// ---------------- scale: dinv/pad from cursor; xs0 = fp16(feat*dinv);
//                  pad bucket to multiple of 8 with sentinel zero-row --------
__global__ void k_scale(const float* __restrict__ feat, int n) {
    int i = blockIdx.x * blockDim.x + threadIdx.x;
    if (i >= n * 32) return;
    int row  = i >> 5;
    int lane = i & 31;
    int deg = g_fill[row];                        // all 32 lanes read it
    deg = min(deg, CAP);
    int pad = min((deg + 7) & ~7, CAP);
    float df = (float)(deg > 0 ? deg : 1);
    float di = rsqrtf(df);
    float2 f = ((const float2*)feat)[i];
    g_xs0[i] = __floats2half2_rn(f.x * di, f.y * di);
    if (lane < pad - deg)                         // <=7 sentinel pads
        g_edges[row * CAP + deg + lane] = N_NODES * 32;
    __syncwarp();                                 // all lanes done with g_fill[row]
    if (lane == 0) {                              // warp owns the row exclusively
        g_degv[row] = pad;
        g_dinv[row] = di;
        g_dsq[row]  = sqrtf(df);
        g_fill[row] = 0;                          // ready for next graph replay
    }
}

// ---------------- gather: warp-per-node, padded buckets, prefetched indices,
//                  batched 8-LDG chunks + fp16 tree reduce (MLP=8) -----------
__device__ __forceinline__ float2 gather_bucket(int node, int pad, int lane,
                                                const __half2* __restrict__ xs) {
    const int* bucket = &g_edges[node * CAP];
    const __half2* xsl = xs + lane;               // per-lane base
    float2 acc = make_float2(0.f, 0.f);
    int s = __ldg(&bucket[lane]);                 // prefetch first 32 indices
    for (int j = 0; j < pad; j += 32) {
        int s_cur = s;
        if (j + 32 < pad)                         // prefetch next 32 (in-bounds: <CAP)
            s = __ldg(&bucket[j + 32 + lane]);
        int cnt = min(32, pad - j);               // multiple of 8
        for (int k = 0; k < cnt; k += 8) {
            // phase 1: all 8 independent loads issue before any consumer
            int a0 = __shfl_sync(0xffffffffu, s_cur, k + 0);
            int a1 = __shfl_sync(0xffffffffu, s_cur, k + 1);
            int a2 = __shfl_sync(0xffffffffu, s_cur, k + 2);
            int a3 = __shfl_sync(0xffffffffu, s_cur, k + 3);
            int a4 = __shfl_sync(0xffffffffu, s_cur, k + 4);
            int a5 = __shfl_sync(0xffffffffu, s_cur, k + 5);
            int a6 = __shfl_sync(0xffffffffu, s_cur, k + 6);
            int a7 = __shfl_sync(0xffffffffu, s_cur, k + 7);
            __half2 v0 = __ldg(xsl + a0);
            __half2 v1 = __ldg(xsl + a1);
            __half2 v2 = __ldg(xsl + a2);
            __half2 v3 = __ldg(xsl + a3);
            __half2 v4 = __ldg(xsl + a4);
            __half2 v5 = __ldg(xsl + a5);
            __half2 v6 = __ldg(xsl + a6);
            __half2 v7 = __ldg(xsl + a7);
            // phase 2: depth-3 fp16 tree, then fp32 flush
            __half2 s01 = __hadd2(v0, v1);
            __half2 s23 = __hadd2(v2, v3);
            __half2 s45 = __hadd2(v4, v5);
            __half2 s67 = __hadd2(v6, v7);
            __half2 s03 = __hadd2(s01, s23);
            __half2 s47 = __hadd2(s45, s67);
            float2 fv = __half22float2(__hadd2(s03, s47));
            acc.x += fv.x;
            acc.y += fv.y;
        }
    }
    return acc;
}

// X1 = -rn*h + (rn-1)*X0 ; writes xs1 = fp16(X1*dinv), out[:,64:128]=relu(X1)
__global__ void k_apply1(const float* __restrict__ feat, const float* __restrict__ lam,
                         float* __restrict__ out, int n) {
    int w    = (blockIdx.x * blockDim.x + threadIdx.x) >> 5;
    int lane = threadIdx.x & 31;
    if (w >= n) return;
    float rn = 2.0f / __ldg(lam);
    float di = g_dinv[w];
    int  pad = __ldg(&g_degv[w]);
    float2 acc = gather_bucket(w, pad, lane, g_xs0);
    float2 x0 = ((const float2*)feat)[w * 32 + lane];
    float2 x1;
    x1.x = -rn * (acc.x * di) + x0.x * (rn - 1.0f);
    x1.y = -rn * (acc.y * di) + x0.y * (rn - 1.0f);
    g_xs1[w * 32 + lane] = __floats2half2_rn(x1.x * di, x1.y * di);
    ((float2*)(out + (size_t)w * 192 + 64))[lane] =
        make_float2(fmaxf(x1.x, 0.f), fmaxf(x1.y, 0.f));
}

// X2 = -2rn*h + 2(rn-1)*X1 - X0 ; X1 recovered as fp16(xs1)*sqrt(deg)
__global__ void k_apply2(const float* __restrict__ feat, const float* __restrict__ lam,
                         float* __restrict__ out, int n) {
    int w    = (blockIdx.x * blockDim.x + threadIdx.x) >> 5;
    int lane = threadIdx.x & 31;
    if (w >= n) return;
    float rn = 2.0f / __ldg(lam);
    float di = g_dinv[w];
    float ds = g_dsq[w];
    int  pad = __ldg(&g_degv[w]);
    float2 acc = gather_bucket(w, pad, lane, g_xs1);
    float2 x0  = ((const float2*)feat)[w * 32 + lane];
    float2 xs1 = __half22float2(g_xs1[w * 32 + lane]);
    float2 x1  = make_float2(xs1.x * ds, xs1.y * ds);
    float2 x2;
    x2.x = -2.0f * rn * (acc.x * di) + 2.0f * (rn - 1.0f) * x1.x - x0.x;
    x2.y = -2.0f * rn * (acc.y * di) + 2.0f * (rn - 1.0f) * x1.y - x0.y;
    ((float2*)(out + (size_t)w * 192 + 128))[lane] =
        make_float2(fmaxf(x2.x, 0.f), fmaxf(x2.y, 0.f));
}

// ---------------- launch ----------------
extern "C" void kernel_launch(void* const* d_in, const int* in_sizes, int n_in,
                              void* d_out, int out_size) {
    const float* feat = (const float*)d_in[0];
    const int*   src  = (const int*)d_in[1];
    const int*   dst  = (const int*)d_in[2];
    const float* lam  = (const float*)d_in[3];
    float* out = (float*)d_out;

    int n = in_sizes[0] / D;     // 60000
    int e = in_sizes[1];         // 1200000

    int eh = (e + 1) >> 1;
    int fmax = (n * 16 > eh) ? n * 16 : eh;
    k_fill_relu<<<(fmax + 255) / 256, 256>>>(src, dst, feat, out, e, n);

    int fthreads = n * 32;
    k_scale <<<(fthreads + 255) / 256, 256>>>(feat, n);
    k_apply1<<<(fthreads + 255) / 256, 256>>>(feat, lam, out, n);
    k_apply2<<<(fthreads + 255) / 256, 256>>>(feat, lam, out, n);
}

// round 13
// speedup vs baseline: 1.1156x; 1.1156x over previous
#include <cuda_runtime.h>
#include <cuda_fp16.h>

#define N_NODES 60000
#define N_EDGES 1200000
#define D 64
#define CAP 128                      // bucket capacity per node (max deg ~50)

// ---------------- scratch (no allocations allowed; zero-init at load) -------
__device__ int     g_fill[N_NODES];          // cursor; re-zeroed each replay
__device__ int     g_degv[N_NODES];          // PADDED degree (multiple of 8)
__device__ int     g_edges[N_NODES * CAP];   // bucketed PRESCALED offs (src*32)
__device__ float   g_dinv[N_NODES];          // 1/sqrt(max(deg,1))
__device__ float   g_dsq [N_NODES];          // sqrt(max(deg,1))
// row N_NODES is a permanent zero row (never written) used by sentinel pads
__device__ __half2 g_xs0[(N_NODES + 1) * 32];  // X0 * dinv (fp16)
__device__ __half2 g_xs1[(N_NODES + 1) * 32];  // X1 * dinv (fp16)

// ---------------- build: atomic fill + float4 relu(X0) stream ---------------
__global__ void k_fill_relu(const int* __restrict__ src, const int* __restrict__ dst,
                            const float* __restrict__ feat, float* __restrict__ out,
                            int e, int n) {
    int i = blockIdx.x * blockDim.x + threadIdx.x;
    if (i < e) {
        int d   = dst[i];
        int pos = atomicAdd(&g_fill[d], 1);
        if (pos < CAP) g_edges[d * CAP + pos] = src[i] * 32;   // half2-unit offset
    }
    if (i < n * 16) {                     // float4 per thread: out[:,0:64]=relu(feat)
        int row = i >> 4;
        int q   = i & 15;
        float4 f = ((const float4*)feat)[i];
        ((float4*)(out + (size_t)row * 192))[q] =
            make_float4(fmaxf(f.x, 0.f), fmaxf(f.y, 0.f),
                        fmaxf(f.z, 0.f), fmaxf(f.w, 0.f));
    }
}

// ---------------- scale: dinv/pad from cursor; xs0 = fp16(feat*dinv);
//                  pad bucket to multiple of 8 with sentinel zero-row --------
__global__ void k_scale(const float* __restrict__ feat, int n) {
    int i = blockIdx.x * blockDim.x + threadIdx.x;
    if (i >= n * 32) return;
    int row  = i >> 5;
    int lane = i & 31;
    int deg = g_fill[row];                        // all 32 lanes read it
    deg = min(deg, CAP);
    int pad = min((deg + 7) & ~7, CAP);
    float df = (float)(deg > 0 ? deg : 1);
    float di = rsqrtf(df);
    float2 f = ((const float2*)feat)[i];
    g_xs0[i] = __floats2half2_rn(f.x * di, f.y * di);
    if (lane < pad - deg)                         // <=7 sentinel pads
        g_edges[row * CAP + deg + lane] = N_NODES * 32;
    __syncwarp();                                 // all lanes done with g_fill[row]
    if (lane == 0) {                              // warp owns the row exclusively
        g_degv[row] = pad;
        g_dinv[row] = di;
        g_dsq[row]  = sqrtf(df);
        g_fill[row] = 0;                          // ready for next graph replay
    }
}

// ---------------- gather: TWO nodes per warp (16 lanes each), uint2 rows ----
// sl = lane & 15 covers feats [4*sl, 4*sl+4). Outer loop runs to padmax
// (warp-converged); per-8-chunk guards are uniform within each 16-lane group;
// shuffles are width-16 with the group's mask (legal under half-warp split).
__device__ __forceinline__ void gather2(int node, int pad, int padmax, int sl,
                                        unsigned gmask, const __half2* __restrict__ xs,
                                        float2& a01, float2& a23) {
    const int* bucket = &g_edges[node * CAP];
    const __half2 hz = __float2half2_rn(0.f);
    for (int j = 0; j < padmax; j += 16) {
        int idx = j + sl;
        int s = __ldg(&bucket[idx < CAP ? idx : 0]);    // clamped, in-bounds
        #pragma unroll
        for (int k = 0; k < 16; k += 8) {
            if (j + k < pad) {                          // uniform per group
                __half2 h0 = hz, h1 = hz;
                #pragma unroll
                for (int kk = 0; kk < 8; kk++) {
                    int sk = __shfl_sync(gmask, s, k + kk, 16);
                    uint2 v = __ldg((const uint2*)(xs + sk) + sl);
                    h0 = __hadd2(h0, *(__half2*)&v.x);
                    h1 = __hadd2(h1, *(__half2*)&v.y);
                }
                float2 f0 = __half22float2(h0);
                float2 f1 = __half22float2(h1);
                a01.x += f0.x; a01.y += f0.y;
                a23.x += f1.x; a23.y += f1.y;
            }
        }
    }
}

// X1 = -rn*h + (rn-1)*X0 ; writes xs1 = fp16(X1*dinv), out[:,64:128]=relu(X1)
__global__ void k_apply1(const float* __restrict__ feat, const float* __restrict__ lam,
                         float* __restrict__ out, int n) {
    int wp   = (blockIdx.x * blockDim.x + threadIdx.x) >> 5;
    int lane = threadIdx.x & 31;
    int g    = lane >> 4;
    int sl   = lane & 15;
    int w    = wp * 2 + g;
    if (w >= n) return;
    unsigned gmask = 0xffffu << (g * 16);
    float rn = 2.0f / __ldg(lam);
    float di = g_dinv[w];
    int  pad = __ldg(&g_degv[w]);
    int  padmax = max(pad, __shfl_xor_sync(0xffffffffu, pad, 16));
    float2 a01 = make_float2(0.f, 0.f), a23 = make_float2(0.f, 0.f);
    gather2(w, pad, padmax, sl, gmask, g_xs0, a01, a23);
    float4 x0 = ((const float4*)feat)[w * 16 + sl];
    float c1 = rn - 1.0f;
    float4 x1;
    x1.x = -rn * (a01.x * di) + x0.x * c1;
    x1.y = -rn * (a01.y * di) + x0.y * c1;
    x1.z = -rn * (a23.x * di) + x0.z * c1;
    x1.w = -rn * (a23.y * di) + x0.w * c1;
    __half2 p0 = __floats2half2_rn(x1.x * di, x1.y * di);
    __half2 p1 = __floats2half2_rn(x1.z * di, x1.w * di);
    ((uint2*)g_xs1)[w * 16 + sl] = make_uint2(*(unsigned*)&p0, *(unsigned*)&p1);
    ((float4*)(out + (size_t)w * 192 + 64))[sl] =
        make_float4(fmaxf(x1.x, 0.f), fmaxf(x1.y, 0.f),
                    fmaxf(x1.z, 0.f), fmaxf(x1.w, 0.f));
}

// X2 = -2rn*h + 2(rn-1)*X1 - X0 ; X1 recovered as fp16(xs1)*sqrt(deg)
__global__ void k_apply2(const float* __restrict__ feat, const float* __restrict__ lam,
                         float* __restrict__ out, int n) {
    int wp   = (blockIdx.x * blockDim.x + threadIdx.x) >> 5;
    int lane = threadIdx.x & 31;
    int g    = lane >> 4;
    int sl   = lane & 15;
    int w    = wp * 2 + g;
    if (w >= n) return;
    unsigned gmask = 0xffffu << (g * 16);
    float rn = 2.0f / __ldg(lam);
    float di = g_dinv[w];
    float ds = g_dsq[w];
    int  pad = __ldg(&g_degv[w]);
    int  padmax = max(pad, __shfl_xor_sync(0xffffffffu, pad, 16));
    float2 a01 = make_float2(0.f, 0.f), a23 = make_float2(0.f, 0.f);
    gather2(w, pad, padmax, sl, gmask, g_xs1, a01, a23);
    float4 x0 = ((const float4*)feat)[w * 16 + sl];
    uint2 xv = ((const uint2*)g_xs1)[w * 16 + sl];
    float2 s0 = __half22float2(*(__half2*)&xv.x);
    float2 s1 = __half22float2(*(__half2*)&xv.y);
    float c2 = 2.0f * (rn - 1.0f);
    float r2 = -2.0f * rn;
    float4 x2;
    x2.x = r2 * (a01.x * di) + c2 * (s0.x * ds) - x0.x;
    x2.y = r2 * (a01.y * di) + c2 * (s0.y * ds) - x0.y;
    x2.z = r2 * (a23.x * di) + c2 * (s1.x * ds) - x0.z;
    x2.w = r2 * (a23.y * di) + c2 * (s1.y * ds) - x0.w;
    ((float4*)(out + (size_t)w * 192 + 128))[sl] =
        make_float4(fmaxf(x2.x, 0.f), fmaxf(x2.y, 0.f),
                    fmaxf(x2.z, 0.f), fmaxf(x2.w, 0.f));
}

// ---------------- launch ----------------
extern "C" void kernel_launch(void* const* d_in, const int* in_sizes, int n_in,
                              void* d_out, int out_size) {
    const float* feat = (const float*)d_in[0];
    const int*   src  = (const int*)d_in[1];
    const int*   dst  = (const int*)d_in[2];
    const float* lam  = (const float*)d_in[3];
    float* out = (float*)d_out;

    int n = in_sizes[0] / D;     // 60000
    int e = in_sizes[1];         // 1200000

    int fmax = (n * 16 > e) ? n * 16 : e;
    k_fill_relu<<<(fmax + 255) / 256, 256>>>(src, dst, feat, out, e, n);

    int sthreads = n * 32;
    k_scale <<<(sthreads + 255) / 256, 256>>>(feat, n);

    int athreads = ((n + 1) / 2) * 32;            // 2 nodes per warp
    k_apply1<<<(athreads + 255) / 256, 256>>>(feat, lam, out, n);
    k_apply2<<<(athreads + 255) / 256, 256>>>(feat, lam, out, n);
}